// round 6
// baseline (speedup 1.0000x reference)
#include <cuda_runtime.h>
#include <math.h>

// ISDALoss_EM on GB300 — round 6.
#define A_DIM 128
#define PITCH 132
#define MAX_S 512
#define MAX_N 4096
#define MAX_C 128

__device__ float g_D[MAX_S * A_DIM];
__device__ float g_U[MAX_S * A_DIM];
__device__ float g_score[MAX_N * 8];
__device__ int   g_labels[MAX_N];
__device__ int   g_ccount[MAX_C];
__device__ int   g_clist[(size_t)MAX_C * MAX_N];

__device__ __forceinline__ void fma2(unsigned long long& d, unsigned long long a,
                                     unsigned long long b) {
    asm("fma.rn.f32x2 %0, %1, %2, %0;" : "+l"(d) : "l"(a), "l"(b));
}
__device__ __forceinline__ unsigned long long pack2(float lo, float hi) {
    unsigned long long r;
    asm("mov.b64 %0, {%1,%2};" : "=l"(r) : "f"(lo), "f"(hi));
    return r;
}
__device__ __forceinline__ float2 unpack2(unsigned long long v) {
    float2 f;
    asm("mov.b64 {%0,%1}, %2;" : "=f"(f.x), "=f"(f.y) : "l"(v));
    return f;
}

// labels: loss init + dtype detect + convert + per-class lists (single block)
__global__ void k_labels(const int* __restrict__ raw, int n, int C,
                         float* out, int writeLoss) {
    __shared__ int odd_nz;
    const int tid = threadIdx.x;
    if (tid == 0) {
        odd_nz = 0;
        if (writeLoss) out[0] = 0.0f;
    }
    if (tid < MAX_C) g_ccount[tid] = 0;
    __syncthreads();
    for (int i = tid; i < n / 2; i += blockDim.x)
        if (raw[2 * i + 1] != 0) atomicOr(&odd_nz, 1);
    __syncthreads();
    if (odd_nz == 0) {
        for (int i = tid; i < n; i += blockDim.x) g_labels[i] = raw[2 * i];
    } else {
        for (int i = tid; i < n; i += blockDim.x) g_labels[i] = raw[i];
    }
    __syncthreads();
    for (int i = tid; i < n; i += blockDim.x) {
        int c = g_labels[i];
        int p = atomicAdd(&g_ccount[c], 1);
        g_clist[(size_t)c * MAX_N + p] = i;
    }
}

// ---- fused: v, blocked Cholesky, D/U, in-smem transpose, class solves -------
__global__ __launch_bounds__(256, 2)
void k_fused(const float* __restrict__ sigma, const float* __restrict__ W,
             const float* __restrict__ F, const float* __restrict__ mu,
             int C, int K) {
    extern __shared__ float sh[];
    float* sA  = sh;                       // 128 * 132
    float* sW  = sA + A_DIM * PITCH;       // 128 * 33
    float* swl = sW + A_DIM * 33;          // 128
    float* sv  = swl + A_DIM;              // 128
    float* srd = sv + A_DIM;               // 128
    float* sdg = srd + A_DIM;              // 128
    float* sD  = sdg + A_DIM;              // 128
    float* sU  = sD + A_DIM;               // 128
    __shared__ float slogdet;

    const int s = blockIdx.x;
    const int cls = s / K;
    const int kk = s - cls * K;
    const int tid = threadIdx.x;
    const int wid = tid >> 5, lane = tid & 31;

    // ---- load Sigma (float4, coalesced), w_l; zero sD ----
    {
        const float4* src4 = reinterpret_cast<const float4*>(sigma + (size_t)s * A_DIM * A_DIM);
        for (int idx = tid; idx < A_DIM * 32; idx += 256) {
            int i = idx >> 5, f = idx & 31;
            *reinterpret_cast<float4*>(&sA[i * PITCH + 4 * f]) = src4[idx];
        }
        if (tid < A_DIM) { swl[tid] = W[cls * A_DIM + tid]; sD[tid] = 0.0f; }
    }
    __syncthreads();

    // ---- v = Sigma @ w_l (before factorization) ----
    if (tid < A_DIM) {
        float acc = 0.0f;
        #pragma unroll 8
        for (int b = 0; b < A_DIM; ++b) acc += sA[b * PITCH + tid] * swl[b];
        sv[tid] = acc;
    }
    __syncthreads();

    // ---- blocked Cholesky (NB = 32) ----
    for (int kb = 0; kb < A_DIM; kb += 32) {
        if (wid == 0) {
            float m[32];
            float* row = &sA[(kb + lane) * PITCH + kb];
            #pragma unroll
            for (int c = 0; c < 32; ++c) m[c] = row[c];
            #pragma unroll
            for (int j = 0; j < 32; ++j) {
                float dj = __shfl_sync(0xffffffffu, m[j], j);
                float l = m[j] * rsqrtf(dj);
                m[j] = l;
                #pragma unroll
                for (int p = j + 1; p < 32; ++p)
                    m[p] -= l * __shfl_sync(0xffffffffu, l, p);
            }
            #pragma unroll
            for (int c = 0; c < 32; ++c)
                if (c <= lane) row[c] = m[c];
            srd[kb + lane] = 1.0f / m[lane];
            sdg[kb + lane] = m[lane];
        }
        __syncthreads();

        const int R = A_DIM - kb - 32;
        if (R > 0) {
            if (tid < R) {
                const int row = kb + 32 + tid;
                float* pr = &sA[row * PITCH + kb];
                const float* pd = &sA[kb * PITCH + kb];
                float x[32];
                #pragma unroll
                for (int c = 0; c < 32; ++c) x[c] = pr[c];
                #pragma unroll
                for (int j = 0; j < 32; ++j) {
                    float a = x[j];
                    #pragma unroll
                    for (int p = 0; p < j; ++p) a -= x[p] * pd[j * PITCH + p];
                    x[j] = a * srd[kb + j];
                }
                #pragma unroll
                for (int c = 0; c < 32; ++c) pr[c] = x[c];
            }
            __syncthreads();

            const int nb = R >> 5;
            const int ntask = nb * (nb + 1);
            for (int task = wid; task < ntask; task += 8) {
                int b = 0, t = task;
                while (t >= 2 * b + 2) { t -= 2 * b + 2; ++b; }
                const int i  = kb + 32 + 32 * b + lane;
                const int j0 = kb + 32 + 16 * t;
                unsigned long long acc[16];
                #pragma unroll
                for (int q = 0; q < 16; ++q) acc[q] = 0ull;
                const float* pa = &sA[i * PITCH + kb];
                #pragma unroll
                for (int k = 0; k < 32; k += 4) {
                    ulonglong2 av = *reinterpret_cast<const ulonglong2*>(pa + k);
                    #pragma unroll
                    for (int q = 0; q < 16; ++q) {
                        ulonglong2 bv = *reinterpret_cast<const ulonglong2*>(
                            &sA[(j0 + q) * PITCH + kb + k]);
                        fma2(acc[q], av.x, bv.x);
                        fma2(acc[q], av.y, bv.y);
                    }
                }
                #pragma unroll
                for (int q = 0; q < 16; ++q) {
                    int col = j0 + q;
                    if (col <= i) {
                        float2 f = unpack2(acc[q]);
                        sA[i * PITCH + col] -= f.x + f.y;
                    }
                }
            }
            __syncthreads();
        }
    }

    // ---- zero strict upper triangle (row-contiguous writes); logdet ----
    for (int idx = tid; idx < A_DIM * A_DIM; idx += 256) {
        int i = idx >> 7, j = idx & 127;
        if (j > i) sA[i * PITCH + j] = 0.0f;
    }
    if (tid < 32) {
        float v = logf(sdg[tid]) + logf(sdg[tid + 32]) +
                  logf(sdg[tid + 64]) + logf(sdg[tid + 96]);
        #pragma unroll
        for (int o = 16; o; o >>= 1) v += __shfl_xor_sync(0xffffffffu, v, o);
        if (tid == 0) slogdet = 2.0f * v;
    }

    // ---- D_c = ||L^T w_c||^2 (register-tiled, packed-pair loads), U_c = v.w_c
    for (int g = 0; g < 4; ++g) {
        __syncthreads();
        for (int idx = tid; idx < 32 * 32; idx += 256) {
            int cc = idx >> 5, f = idx & 31;
            int c = 32 * g + cc;
            float4 wv = (c < C) ? reinterpret_cast<const float4*>(W + (size_t)c * A_DIM)[f]
                                : make_float4(0.f, 0.f, 0.f, 0.f);
            sW[(4 * f + 0) * 33 + cc] = wv.x;
            sW[(4 * f + 1) * 33 + cc] = wv.y;
            sW[(4 * f + 2) * 33 + cc] = wv.z;
            sW[(4 * f + 3) * 33 + cc] = wv.w;
        }
        __syncthreads();

        const int t = (g & 1) ? (7 - wid) : wid;
        const int j0 = 16 * t;
        unsigned long long acc[8];
        #pragma unroll
        for (int q = 0; q < 8; ++q) acc[q] = 0ull;
        float u = 0.0f;
        const bool doU = (t == 0);

        #pragma unroll 2
        for (int i = j0; i < A_DIM; ++i) {
            const ulonglong2* Lr = reinterpret_cast<const ulonglong2*>(&sA[i * PITCH + j0]);
            ulonglong2 p0 = Lr[0];
            ulonglong2 p1 = Lr[1];
            float wv = sW[i * 33 + lane];
            unsigned long long w2 = pack2(wv, wv);
            fma2(acc[0], p0.x, w2);
            fma2(acc[1], p0.y, w2);
            fma2(acc[2], p1.x, w2);
            fma2(acc[3], p1.y, w2);
            ulonglong2 p2 = Lr[2];
            ulonglong2 p3 = Lr[3];
            fma2(acc[4], p2.x, w2);
            fma2(acc[5], p2.y, w2);
            fma2(acc[6], p3.x, w2);
            fma2(acc[7], p3.y, w2);
            if (doU) u += sv[i] * wv;
        }
        unsigned long long d2 = 0ull;
        #pragma unroll
        for (int q = 0; q < 8; ++q) fma2(d2, acc[q], acc[q]);
        float2 dd = unpack2(d2);
        int c = 32 * g + lane;
        atomicAdd(&sD[c], dd.x + dd.y);
        if (doU) sU[c] = u;
    }
    __syncthreads();

    for (int c = tid; c < C; c += 256) {
        g_D[s * A_DIM + c] = sD[c];
        g_U[s * A_DIM + c] = sU[c];
    }

    // ---- transpose lower -> upper (dest-contiguous writes); stale lower is
    //      harmless: solve only consumes already-retired components from it.
    for (int idx = tid; idx < A_DIM * A_DIM; idx += 256) {
        int j = idx >> 7, i = idx & 127;
        if (i > j) sA[j * PITCH + i] = sA[i * PITCH + j];
    }
    __syncthreads();

    // ---- class-grouped solves: score = dist + logdet, 4 samples per warp ----
    const int cnt = g_ccount[cls];
    const float logd = slogdet;
    const float4* F4 = reinterpret_cast<const float4*>(F);
    const float4 mv = reinterpret_cast<const float4*>(mu)[(size_t)s * 32 + lane];

    for (int m0 = wid * 4; m0 < cnt; m0 += 32) {
        int n[4];
        bool has[4];
        #pragma unroll
        for (int r = 0; r < 4; ++r) {
            has[r] = (m0 + r) < cnt;
            n[r] = g_clist[(size_t)cls * MAX_N + (has[r] ? (m0 + r) : m0)];
        }
        float d[4][4], dist[4];
        #pragma unroll
        for (int r = 0; r < 4; ++r) {
            float4 fv = F4[(size_t)n[r] * 32 + lane];
            d[r][0] = fv.x - mv.x; d[r][1] = fv.y - mv.y;
            d[r][2] = fv.z - mv.z; d[r][3] = fv.w - mv.w;
            dist[r] = 0.0f;
        }
        #pragma unroll 4
        for (int j = 0; j < A_DIM; ++j) {
            float4 col = *reinterpret_cast<const float4*>(&sA[j * PITCH + 4 * lane]);
            float rdj = srd[j];
            int owner = j >> 2, q = j & 3;
            #pragma unroll
            for (int r = 0; r < 4; ++r) {
                float dq = (q == 0) ? d[r][0] : (q == 1) ? d[r][1]
                         : (q == 2) ? d[r][2] : d[r][3];
                float z = __shfl_sync(0xffffffffu, dq, owner) * rdj;
                dist[r] += z * z;
                d[r][0] -= col.x * z;
                d[r][1] -= col.y * z;
                d[r][2] -= col.z * z;
                d[r][3] -= col.w * z;
            }
        }
        if (lane == 0) {
            #pragma unroll
            for (int r = 0; r < 4; ++r)
                if (has[r]) g_score[n[r] * 8 + kk] = dist[r] + logd;
        }
    }
}

// ---------------- fused y = F W^T + b, argmin, aug, log-softmax, loss --------
#define NB 8
__global__ __launch_bounds__(256, 3)
void k_yloss(const float* __restrict__ F, const float* __restrict__ W,
             const float* __restrict__ bias, const float* __restrict__ ratioPtr,
             float* __restrict__ yout, float* __restrict__ lossout,
             int N, int C, int K, int writeLoss) {
    extern __shared__ float sh[];
    float* sWT = sh;                       // [128][C]
    float* sF  = sWT + A_DIM * C;          // [NB][128]
    float* sY  = sF + NB * A_DIM;          // [NB][C]  (y, then aug in-place)
    float* sB  = sY + NB * C;              // [C]
    const int tid = threadIdx.x;
    const int n0 = blockIdx.x * NB;

    for (int idx = tid; idx < C * A_DIM; idx += 256) {
        int c = idx >> 7, aa = idx & 127;
        sWT[aa * C + c] = W[idx];
    }
    for (int idx = tid; idx < NB * A_DIM; idx += 256) {
        int nl = idx >> 7;
        int n = n0 + nl;
        sF[idx] = (n < N) ? F[(size_t)n * A_DIM + (idx & 127)] : 0.0f;
    }
    for (int c = tid; c < C; c += 256) sB[c] = bias[c];
    __syncthreads();

    const int warp = tid >> 5, lane = tid & 31;
    const int nchunk = (C + 31) >> 5;

    for (int task = warp; task < NB * nchunk; task += 8) {
        int nl = task / nchunk;
        int c = (task - nl * nchunk) * 32 + lane;
        int n = n0 + nl;
        if (c < C && n < N) {
            float acc = sB[c];
            const float* f = sF + nl * A_DIM;
            #pragma unroll
            for (int aa = 0; aa < A_DIM; aa += 4) {
                float4 fv = *reinterpret_cast<const float4*>(f + aa);
                acc += fv.x * sWT[aa * C + c];
                acc += fv.y * sWT[(aa + 1) * C + c];
                acc += fv.z * sWT[(aa + 2) * C + c];
                acc += fv.w * sWT[(aa + 3) * C + c];
            }
            sY[nl * C + c] = acc;
            yout[(size_t)n * C + c] = acc;
        }
    }
    __syncthreads();

    // epilogue: warp per sample; aug written into sY in place
    const float hr = 0.5f * ratioPtr[0];
    const int nl = warp;
    const int n = n0 + nl;
    if (n < N) {
        int l = g_labels[n];
        const float* sc = g_score + n * 8;
        int k = 0;
        float best = sc[0];
        for (int kkk = 1; kkk < K; ++kkk) {
            float v = sc[kkk];
            if (v < best) { best = v; k = kkk; }
        }
        int s = l * K + k;
        const float* Dp = g_D + s * A_DIM;
        const float* Up = g_U + s * A_DIM;
        float ul = Up[l];
        float* aug = sY + nl * C;

        float mymax = -INFINITY;
        for (int m = 0; m < nchunk; ++m) {
            int c = lane + 32 * m;
            if (c < C) {
                float v = aug[c] + hr * (Dp[c] - 2.0f * Up[c] + ul);
                aug[c] = v;
                mymax = fmaxf(mymax, v);
            }
        }
        #pragma unroll
        for (int o = 16; o; o >>= 1)
            mymax = fmaxf(mymax, __shfl_xor_sync(0xffffffffu, mymax, o));
        __syncwarp();
        float sum = 0.0f;
        for (int m = 0; m < nchunk; ++m) {
            int c = lane + 32 * m;
            if (c < C) sum += expf(aug[c] - mymax);
        }
        #pragma unroll
        for (int o = 16; o; o >>= 1) sum += __shfl_xor_sync(0xffffffffu, sum, o);
        if (lane == 0 && writeLoss) {
            float lse = mymax + logf(sum);
            atomicAdd(lossout, (lse - aug[l]) / (float)N);
        }
    }
}

// ---------------- launch -----------------------------------------------------
extern "C" void kernel_launch(void* const* d_in, const int* in_sizes, int n_in,
                              void* d_out, int out_size) {
    const float* F     = (const float*)d_in[0];
    const float* W     = (const float*)d_in[1];
    const float* bias  = (const float*)d_in[2];
    const float* mu    = (const float*)d_in[4];
    const float* sigma = (const float*)d_in[5];
    const int*   lraw  = (const int*)d_in[6];
    const float* ratio = (const float*)d_in[7];

    const int C = in_sizes[2];
    const int K = in_sizes[3] / C;
    const int Ad = in_sizes[1] / C;
    const int N = in_sizes[0] / Ad;
    const int S = C * K;

    float* out = (float*)d_out;
    const int yoff = out_size - N * C;
    const int writeLoss = (yoff >= 1) ? 1 : 0;
    float* yout = out + (yoff > 0 ? yoff : 0);

    const int smem_fused = (A_DIM * PITCH + A_DIM * 33 + 6 * A_DIM) * 4;   // 87552
    const int smem_yl    = (A_DIM * C + NB * A_DIM + NB * C + C) * 4;      // 58896

    cudaFuncSetAttribute(k_fused, cudaFuncAttributeMaxDynamicSharedMemorySize, smem_fused);
    cudaFuncSetAttribute(k_yloss, cudaFuncAttributeMaxDynamicSharedMemorySize, smem_yl);

    k_labels<<<1, 256>>>(lraw, N, C, out, writeLoss);
    k_fused<<<S, 256, smem_fused>>>(sigma, W, F, mu, C, K);
    k_yloss<<<(N + NB - 1) / NB, 256, smem_yl>>>(F, W, bias, ratio, yout, out,
                                                 N, C, K, writeLoss);
}